// round 15
// baseline (speedup 1.0000x reference)
#include <cuda_runtime.h>
#include <cstdint>

// CRF negative log-likelihood on GB300 (sm_103a).
// B=512, S=1024, T=32. Forward/backward split at m=(S-1)/2:
//   Z = sum_t alpha_t(m) * beta_t(m).
// R14: TWO sequences per chain warp, packed f32x2 end-to-end. Lane t holds
// (a_s0[t], a_s1[t]) in one u64; E is seq-invariant so E2[i]=(E,E). STS/BAR/
// add-tree/blend amortize over 2 seqs; chain warps halve (1024->512, ~0.86/
// SMSP) killing the issue contention that bound R13 (~219 cyc/step measured
// vs ~120 latency floor). BWD symmetrized: v' = pe * beta' exactly.
// Chain core otherwise unchanged: SMEM broadcast (STS.64 + BAR@nw=1 + 16x
// LDS.128 volatile), 32x FFMA2, raw prefetch (PF=8) converted at consumption,
// rescale every 4 steps off-chain, ONE packed chain FMA per step.

#define FULLMASK 0xFFFFFFFFu
#define SFIX 1024                      // problem shape is fixed

__device__ float g_vec[2][2048][32];   // [dir][seq][tag] boundary vectors
__device__ float g_C[2][2048];         // [dir][seq] log2 offsets

typedef unsigned long long ull;

__device__ __forceinline__ float ex2f(float x) {
    float r; asm("ex2.approx.ftz.f32 %0, %1;" : "=f"(r) : "f"(x)); return r;
}
__device__ __forceinline__ float lg2f(float x) {
    float r; asm("lg2.approx.ftz.f32 %0, %1;" : "=f"(r) : "f"(x)); return r;
}
__device__ __forceinline__ ull packf2(float lo, float hi) {
    ull d; asm("mov.b64 %0, {%1, %2};" : "=l"(d) : "f"(lo), "f"(hi)); return d;
}
__device__ __forceinline__ void unpackf2(ull d, float& lo, float& hi) {
    asm("mov.b64 {%0, %1}, %2;" : "=f"(lo), "=f"(hi) : "l"(d));
}
__device__ __forceinline__ ull fma2(ull a, ull b, ull c) {
    ull d; asm("fma.rn.f32x2 %0, %1, %2, %3;" : "=l"(d) : "l"(a), "l"(b), "l"(c));
    return d;
}
__device__ __forceinline__ ull add2(ull a, ull b) {
    ull d; asm("add.rn.f32x2 %0, %1, %2;" : "=l"(d) : "l"(a), "l"(b));
    return d;
}
__device__ __forceinline__ ull mul2(ull a, ull b) {
    ull d; asm("mul.rn.f32x2 %0, %1, %2;" : "=l"(d) : "l"(a), "l"(b));
    return d;
}
__device__ __forceinline__ ull sub2(ull a, ull b) {
    // a - b via fma: a + (-1)*b
    ull d;
    asm("fma.rn.f32x2 %0, %1, %2, %3;"
        : "=l"(d) : "l"(0xBF800000BF800000ull), "l"(b), "l"(a));
    return d;
}

// ---------------- one direction, TWO sequences packed ----------------------
// FWD: alpha over s=1..M (M steps), broadcast value = packed alpha.
// BWD: beta from S-1 down to M (S-1-M steps), broadcast v = pe_s*beta_s packed.
template <bool FWD>
__device__ __forceinline__ void run_dir2(
    int w, int t, ull* pbuf,
    const float* __restrict__ emis, const float* __restrict__ mask,
    const float* __restrict__ trans, const float* __restrict__ startT,
    const float* __restrict__ endT)
{
    constexpr int T = 32;
    constexpr int S = SFIX;
    constexpr float LOG2E = 1.4426950408889634f;
    constexpr int PF = 8;
    constexpr int M = (S - 1) / 2;                 // 511
    constexpr int NSTEP = FWD ? M : (S - 1 - M);   // 511 / 512
    constexpr int NBLK = NSTEP / PF;               // 63 / 64
    constexpr int NREM = NSTEP % PF;               // 7 / 0
    constexpr int ESTRIDE = S * T;                 // seq1 emission offset (elems)

    const int s0 = 2 * w;                          // this warp's two sequences
    const long base0 = (long)s0 * S;

    // E pairs (seq-invariant, replicated in both halves). FWD: col t; BWD: row t.
    ull E2[32];
    #pragma unroll
    for (int i = 0; i < 32; i++) {
        float e = ex2f((FWD ? trans[i * T + t] : trans[t * T + i]) * LOG2E);
        E2[i] = packf2(e, e);
    }

    // init (both seqs)
    const float il0 = FWD ? (startT[t] + emis[ base0      * T + t]) : endT[t];
    const float il1 = FWD ? (startT[t] + emis[(base0 + S) * T + t]) : endT[t];
    const float b0  = il0 * LOG2E, b1 = il1 * LOG2E;
    float C0 = __shfl_sync(FULLMASK, b0, 0);
    float C1 = __shfl_sync(FULLMASK, b1, 0);
    ull av = packf2(ex2f(b0 - C0), ex2f(b1 - C1));  // FWD: alpha. BWD: beta.
    ull v  = av;                                    // BWD broadcast value
    if (!FWD) {
        float p0 = ex2f(emis[(base0 + S - 1) * T + t] * LOG2E);
        float p1 = ex2f(emis[(base0 + 2 * S - 1) * T + t] * LOG2E);
        v = mul2(av, packf2(p0, p1));
    }

    // RAW prefetch. FWD: pe&mask at pos 1+k. BWD: pe at S-2-k, mask at S-1-k.
    float rawe0[PF], rawe1[PF], rawm0[PF], rawm1[PF];
    #pragma unroll
    for (int k = 0; k < PF; k++) {
        const int pe_pos = FWD ? (1 + k) : (S - 2 - k);
        const int mk_pos = FWD ? (1 + k) : (S - 1 - k);
        rawe0[k] = emis[(base0 + pe_pos) * T + t];
        rawe1[k] = emis[(base0 + S + pe_pos) * T + t];
        rawm0[k] = mask[base0 + mk_pos];
        rawm1[k] = mask[base0 + S + mk_pos];
    }
    // Strength-reduced prefetch pointers; seq1 via immediate offsets.
    // Clamp-free: positions stay within [0, S-1] for all prefetches used.
    const float* pe_pf = emis + (base0 + (FWD ? (1 + PF) : (S - 2 - PF))) * T + t;
    const float* pm_pf = mask + base0 + (FWD ? (1 + PF) : (S - 1 - PF));

    const uint32_t sbase = (uint32_t)__cvta_generic_to_shared(pbuf);

    auto step = [&](int j, int slot, bool do_rescale) {
        // emission exp2 (off-chain: hidden under broadcast round)
        const ull pep = packf2(ex2f(rawe0[slot] * LOG2E),
                               ex2f(rawe1[slot] * LOG2E));
        const ull mkp = packf2(rawm0[slot], rawm1[slot]);
        rawe0[slot] = pe_pf[0];
        rawe1[slot] = pe_pf[ESTRIDE];
        rawm0[slot] = pm_pf[0];
        rawm1[slot] = pm_pf[S];
        pe_pf += FWD ? T : -T;
        pm_pf += FWD ? 1 : -1;

        ull scalep = 0x3F8000003F800000ull;        // (1.0f, 1.0f)
        if (do_rescale) {                          // every 4 steps, off-chain
            const ull m64 = __shfl_sync(FULLMASK, FWD ? av : v, 0);
            unsigned e0 = ((unsigned)(m64) >> 23) & 0xFFu;
            unsigned e1 = ((unsigned)(m64 >> 32) >> 23) & 0xFFu;
            e0 = (e0 < 1u) ? 1u : ((e0 > 253u) ? 253u : e0);
            e1 = (e1 < 1u) ? 1u : ((e1 > 253u) ? 253u : e1);
            scalep = ((ull)((254u - e1) << 23) << 32) | (ull)((254u - e0) << 23);
            C0 += (float)((int)e0 - 127);
            C1 += (float)((int)e1 - 127);
        }
        const ull mks = mul2(mkp, scalep);         // off-chain
        const ull bas = mul2(sub2(scalep, mks), av);

        // broadcast packed state (256B per buffer, double-buffered)
        const uint32_t off = sbase + ((j & 1) << 8);
        pbuf[((j & 1) << 5) + t] = FWD ? av : v;
        __syncthreads();                           // BAR @nw=1, drains STS

        // matvec: 16x LDS.128 (broadcast) + 32x FFMA2, 8 packed accumulators
        ull acc[8] = {0ull,0ull,0ull,0ull,0ull,0ull,0ull,0ull};
        #pragma unroll
        for (int jj = 0; jj < 16; jj++) {
            ull q0, q1;
            asm volatile("ld.shared.v2.u64 {%0, %1}, [%2];"
                : "=l"(q0), "=l"(q1) : "r"(off + 16u * jj) : "memory");
            acc[(2 * jj)     & 7] = fma2(q0, E2[2 * jj],     acc[(2 * jj)     & 7]);
            acc[(2 * jj + 1) & 7] = fma2(q1, E2[2 * jj + 1], acc[(2 * jj + 1) & 7]);
        }
        acc[0] = add2(acc[0], acc[1]);
        acc[2] = add2(acc[2], acc[3]);
        acc[4] = add2(acc[4], acc[5]);
        acc[6] = add2(acc[6], acc[7]);
        acc[0] = add2(acc[0], acc[2]);
        acc[4] = add2(acc[4], acc[6]);
        const ull ysum = add2(acc[0], acc[4]);     // packed (y0, y1)

        if (FWD) {
            av = fma2(mul2(mks, pep), ysum, bas);  // ONE packed chain FMA
        } else {
            av = fma2(mks, ysum, bas);             // packed beta
            v  = mul2(av, pep);                    // v' = pe * beta' (exact)
        }
    };

    int j = 0;
    for (int blk = 0; blk < NBLK; blk++) {
        #pragma unroll
        for (int u = 0; u < PF; u++, j++) step(j, u, (u & 3) == 3);
    }
    #pragma unroll
    for (int u = 0; u < NREM; u++, j++) step(j, u, (u & 3) == 3);

    float a0, a1; unpackf2(av, a0, a1);
    g_vec[FWD ? 0 : 1][s0][t]     = a0;
    g_vec[FWD ? 0 : 1][s0 + 1][t] = a1;
    if (t == 0) {
        g_C[FWD ? 0 : 1][s0]     = C0;
        g_C[FWD ? 0 : 1][s0 + 1] = C1;
    }
}

// ---------------- gold score path (independent of chains) ------------------
__device__ __forceinline__ void run_score(
    int b, int t,
    const float* __restrict__ emis, const int* __restrict__ tags32,
    const float* __restrict__ mask, const float* __restrict__ trans,
    const float* __restrict__ startT, const float* __restrict__ endT,
    float* __restrict__ out)
{
    constexpr int T = 32;
    constexpr int S = SFIX;
    const long base = (long)b * S;

    // detect int64 vs int32 tag layout (little-endian)
    int nz = 0;
    for (int k = t; k < 128; k += 32) nz |= tags32[2 * k + 1];
    nz = __reduce_or_sync(FULLMASK, nz);
    const bool is64 = (nz == 0);

    float sc = 0.0f, msum = 0.0f;
    #pragma unroll 4
    for (int s = t; s < S; s += 32) {
        float mk = mask[base + s];
        msum += mk;
        if (s >= 1) {
            long ic = base + s, ip = base + s - 1;
            int tc = is64 ? tags32[2 * ic] : tags32[ic];
            int tp = is64 ? tags32[2 * ip] : tags32[ip];
            sc += (emis[ic * T + tc] + trans[tp * T + tc]) * mk;
        }
    }
    #pragma unroll
    for (int d = 16; d; d >>= 1) {
        sc   += __shfl_xor_sync(FULLMASK, sc, d);
        msum += __shfl_xor_sync(FULLMASK, msum, d);
    }

    if (t == 0) {
        const int last = (int)(msum + 0.5f) - 1;
        long i0 = base, il = base + last;
        int tg0 = is64 ? tags32[2 * i0] : tags32[i0];
        int tgl = is64 ? tags32[2 * il] : tags32[il];
        const float score = sc + startT[tg0] + emis[i0 * T + tg0] + endT[tgl];
        atomicAdd(out, -score);            // out accumulates -sum(score)
    }
}

// ---------------- fused launch: fwd-pairs | bwd-pairs | score --------------
__global__ void __launch_bounds__(32) crf_fused_kernel(
    const float* __restrict__ emis,
    const int*   __restrict__ tags32,
    const float* __restrict__ mask,
    const float* __restrict__ trans,
    const float* __restrict__ startT,
    const float* __restrict__ endT,
    float* __restrict__ out,
    int B)
{
    __shared__ __align__(16) ull pbuf[64];     // 2 buffers x 32 packed values
    const int t = threadIdx.x;
    const int blk = blockIdx.x;
    const int H = B / 2;                       // chain CTAs per direction

    if (blk < H) {
        run_dir2<true >(blk, t, pbuf, emis, mask, trans, startT, endT);
    } else if (blk < 2 * H) {
        run_dir2<false>(blk - H, t, pbuf, emis, mask, trans, startT, endT);
    } else {
        run_score(blk - 2 * H, t, emis, tags32, mask, trans, startT, endT, out);
    }
}

// ---------------- combine: alpha.beta dot -> partition ---------------------
__global__ void __launch_bounds__(32) crf_combine_kernel(float* __restrict__ out)
{
    constexpr float LN2 = 0.6931471805599453f;
    const int b = blockIdx.x;
    const int t = threadIdx.x;

    float p = g_vec[0][b][t] * g_vec[1][b][t];
    #pragma unroll
    for (int d = 16; d; d >>= 1) p += __shfl_xor_sync(FULLMASK, p, d);
    const float partition = (g_C[0][b] + g_C[1][b] + lg2f(p)) * LN2;

    if (t == 0) atomicAdd(out, partition);
}

extern "C" void kernel_launch(void* const* d_in, const int* in_sizes, int n_in,
                              void* d_out, int out_size) {
    const float* emis   = (const float*)d_in[0];   // [B,S,T] float32
    const int*   tags   = (const int*)  d_in[1];   // [B,S] int (32/64 detected)
    const float* mask   = (const float*)d_in[2];   // [B,S] float32
    const float* trans  = (const float*)d_in[3];   // [T,T]
    const float* startT = (const float*)d_in[4];   // [T]
    const float* endT   = (const float*)d_in[5];   // [T]
    float* out = (float*)d_out;

    const int B = in_sizes[2] / SFIX;              // mask elements = B*S (B even)

    cudaMemsetAsync(out, 0, sizeof(float));        // memset node, no kernel
    crf_fused_kernel<<<2 * (B / 2) + B, 32>>>(emis, tags, mask, trans,
                                              startT, endT, out, B);
    crf_combine_kernel<<<B, 32>>>(out);
}

// round 16
// speedup vs baseline: 2.3012x; 2.3012x over previous
#include <cuda_runtime.h>
#include <cstdint>

// CRF negative log-likelihood on GB300 (sm_103a).
// B=512, S=1024, T=32. Forward/backward split at m=(S-1)/2:
//   Z = sum_t alpha_t(m) * beta_t(m).
// Fused launch grid=3B: [0,B) fwd chains, [B,2B) bwd chains, [2B,3B) score.
// R16 (on top of R13 win; R15's 2-seq packing reverted — per-warp issue-bound):
//  - NO per-step barrier: single-warp CTA, volatile STS -> volatile LDS are
//    ordered by the in-order LSU pipe (convergent, lockstep). BAR's effective
//    ~47cyc + deferred-block release removed from every step.
//  - prefetch LDGs moved AFTER the MAC so broadcast LDS wavefronts don't queue
//    behind them in L1tex.
// Chain core: SMEM broadcast, 8x LDS.128 + 16x FFMA2 (exp(trans) in regs),
// raw prefetch (PF=8) converted at consumption, rescale every 4 steps
// off-chain, ONE serial-chain FMA per step.

#define FULLMASK 0xFFFFFFFFu
#define SFIX 1024                      // problem shape is fixed

__device__ float g_vec[2][2048][32];   // [dir][seq][tag] boundary vectors
__device__ float g_C[2][2048];         // [dir][seq] log2 offsets

__device__ __forceinline__ float ex2f(float x) {
    float r; asm("ex2.approx.ftz.f32 %0, %1;" : "=f"(r) : "f"(x)); return r;
}
__device__ __forceinline__ float lg2f(float x) {
    float r; asm("lg2.approx.ftz.f32 %0, %1;" : "=f"(r) : "f"(x)); return r;
}
__device__ __forceinline__ unsigned long long packf2(float lo, float hi) {
    unsigned long long d; asm("mov.b64 %0, {%1, %2};" : "=l"(d) : "f"(lo), "f"(hi)); return d;
}
__device__ __forceinline__ void unpackf2(unsigned long long d, float& lo, float& hi) {
    asm("mov.b64 {%0, %1}, %2;" : "=f"(lo), "=f"(hi) : "l"(d));
}
__device__ __forceinline__ unsigned long long fma2(unsigned long long a,
                                                   unsigned long long b,
                                                   unsigned long long c) {
    unsigned long long d;
    asm("fma.rn.f32x2 %0, %1, %2, %3;" : "=l"(d) : "l"(a), "l"(b), "l"(c));
    return d;
}
__device__ __forceinline__ unsigned long long add2(unsigned long long a,
                                                   unsigned long long b) {
    unsigned long long d;
    asm("add.rn.f32x2 %0, %1, %2;" : "=l"(d) : "l"(a), "l"(b));
    return d;
}

// dot of broadcast slab with this lane's matrix pairs: 8x LDS.128 + 16x FFMA2
__device__ __forceinline__ float matvec_dot(uint32_t off, const unsigned long long* M2) {
    unsigned long long acc0 = 0ull, acc1 = 0ull, acc2 = 0ull, acc3 = 0ull;
    #pragma unroll
    for (int jj = 0; jj < 4; jj++) {
        unsigned long long q0, q1, q2, q3;
        asm volatile("ld.shared.v2.u64 {%0, %1}, [%2];"
            : "=l"(q0), "=l"(q1) : "r"(off + 32u * jj) : "memory");
        asm volatile("ld.shared.v2.u64 {%0, %1}, [%2 + 16];"
            : "=l"(q2), "=l"(q3) : "r"(off + 32u * jj) : "memory");
        acc0 = fma2(q0, M2[4 * jj + 0], acc0);
        acc1 = fma2(q1, M2[4 * jj + 1], acc1);
        acc2 = fma2(q2, M2[4 * jj + 2], acc2);
        acc3 = fma2(q3, M2[4 * jj + 3], acc3);
    }
    acc0 = add2(acc0, acc1);
    acc2 = add2(acc2, acc3);
    acc0 = add2(acc0, acc2);
    float lo, hi; unpackf2(acc0, lo, hi);
    return lo + hi;
}

// ---------------- one direction of the recursion ---------------------------
// FWD: alpha over s=1..M (M steps), broadcast value = alpha.
// BWD: beta from S-1 down to M (S-1-M steps), broadcast value v = pe_s*beta_s.
template <bool FWD>
__device__ __forceinline__ void run_dir(
    int b, int t, float* pbuf,
    const float* __restrict__ emis, const float* __restrict__ mask,
    const float* __restrict__ trans, const float* __restrict__ startT,
    const float* __restrict__ endT)
{
    constexpr int T = 32;
    constexpr int S = SFIX;
    constexpr float LOG2E = 1.4426950408889634f;
    constexpr int PF = 8;
    constexpr int M = (S - 1) / 2;                 // 511
    constexpr int NSTEP = FWD ? M : (S - 1 - M);   // 511 / 512
    constexpr int NBLK = NSTEP / PF;               // 63 / 64
    constexpr int NREM = NSTEP % PF;               // 7 / 0

    const long base = (long)b * S;

    // matrix for this lane, packed f32x2. FWD: column t; BWD: row t.
    unsigned long long M2[16];
    #pragma unroll
    for (int j = 0; j < 16; j++) {
        float lo = ex2f((FWD ? trans[(2 * j) * T + t]     : trans[t * T + 2 * j])     * LOG2E);
        float hi = ex2f((FWD ? trans[(2 * j + 1) * T + t] : trans[t * T + 2 * j + 1]) * LOG2E);
        M2[j] = packf2(lo, hi);
    }

    // init
    const float il  = FWD ? (startT[t] + emis[base * T + t]) : endT[t];
    const float al0 = il * LOG2E;
    float C = __shfl_sync(FULLMASK, al0, 0);
    float a = ex2f(al0 - C);                   // FWD: alpha. BWD: beta.
    float v = a;                               // BWD broadcast value
    if (!FWD) v = a * ex2f(emis[(base + S - 1) * T + t] * LOG2E);

    // RAW prefetch. FWD: pe&mask at pos 1+k. BWD: pe at S-2-k, mask at S-1-k.
    float rawe[PF], rawm[PF];
    #pragma unroll
    for (int k = 0; k < PF; k++) {
        rawe[k] = emis[(base + (FWD ? (1 + k) : (S - 2 - k))) * T + t];
        rawm[k] = mask[base + (FWD ? (1 + k) : (S - 1 - k))];
    }
    // Strength-reduced prefetch pointers (position of step j+PF at step j).
    // Clamp-free: max FWD pos = NSTEP+PF < S-1; min BWD pos = M-PF >= 0.
    const float* pe_pf = emis + (base + (FWD ? (1 + PF) : (S - 2 - PF))) * T + t;
    const float* pm_pf = mask + base + (FWD ? (1 + PF) : (S - 1 - PF));

    const uint32_t sbase  = (uint32_t)__cvta_generic_to_shared(pbuf);
    const uint32_t sbaset = sbase + 4u * (uint32_t)t;      // this lane's slot

    auto step = [&](int j, int slot, bool do_rescale) {
        const float pe = ex2f(rawe[slot] * LOG2E);   // off-chain (hidden)
        const float mk = rawm[slot];

        float scale = 1.0f;
        if (do_rescale) {                 // every 4 steps, off-chain (shfl hidden)
            const float m0 = __shfl_sync(FULLMASK, FWD ? a : v, 0);
            unsigned ex = (__float_as_uint(m0) >> 23) & 0xFFu;
            ex = (ex < 1u) ? 1u : ((ex > 253u) ? 253u : ex);
            scale = __uint_as_float((254u - ex) << 23);      // 2^(127-ex)
            C += (float)((int)ex - 127);
        }
        const float mks = mk * scale;                // off-chain
        const float bas = (scale - mks) * a;         // (1-mk)*scale*a, off-chain

        // ---- broadcast WITHOUT barrier: single-warp CTA, convergent; the
        // in-order LSU pipe orders this volatile STS before the volatile LDSs
        // in matvec_dot. Double-buffered (WAR separated by program order).
        const uint32_t off = sbase + ((j & 1) << 7);
        asm volatile("st.shared.b32 [%0], %1;"
            :: "r"(sbaset + ((j & 1) << 7)), "f"(FWD ? a : v) : "memory");

        const float ysum = matvec_dot(off, M2);

        // ---- prefetch AFTER the MAC: LDGs queue behind the critical LDSs,
        // not in front of them, in the shared L1tex pipe. Consumed PF steps on.
        rawe[slot] = *pe_pf;  pe_pf += FWD ? T : -T;
        rawm[slot] = *pm_pf;  pm_pf += FWD ? 1 : -1;

        if (FWD) {
            a = fmaf(mks * pe, ysum, bas);           // ONE chain FMA
        } else {
            v = fmaf(mks * pe, ysum, bas * pe);      // chain FMA (pe = next pos)
            a = fmaf(mks,      ysum, bas);           // beta, parallel FMA
        }
    };

    int j = 0;
    for (int blk = 0; blk < NBLK; blk++) {
        #pragma unroll
        for (int u = 0; u < PF; u++, j++) step(j, u, (u & 3) == 3);
    }
    #pragma unroll
    for (int u = 0; u < NREM; u++, j++) step(j, u, (u & 3) == 3);

    g_vec[FWD ? 0 : 1][b][t] = a;
    if (t == 0) g_C[FWD ? 0 : 1][b] = C;
}

// ---------------- gold score path (independent of chains) ------------------
__device__ __forceinline__ void run_score(
    int b, int t,
    const float* __restrict__ emis, const int* __restrict__ tags32,
    const float* __restrict__ mask, const float* __restrict__ trans,
    const float* __restrict__ startT, const float* __restrict__ endT,
    float* __restrict__ out)
{
    constexpr int T = 32;
    constexpr int S = SFIX;
    const long base = (long)b * S;

    // detect int64 vs int32 tag layout (little-endian)
    int nz = 0;
    for (int k = t; k < 128; k += 32) nz |= tags32[2 * k + 1];
    nz = __reduce_or_sync(FULLMASK, nz);
    const bool is64 = (nz == 0);

    float sc = 0.0f, msum = 0.0f;
    #pragma unroll 4
    for (int s = t; s < S; s += 32) {
        float mk = mask[base + s];
        msum += mk;
        if (s >= 1) {
            long ic = base + s, ip = base + s - 1;
            int tc = is64 ? tags32[2 * ic] : tags32[ic];
            int tp = is64 ? tags32[2 * ip] : tags32[ip];
            sc += (emis[ic * T + tc] + trans[tp * T + tc]) * mk;
        }
    }
    #pragma unroll
    for (int d = 16; d; d >>= 1) {
        sc   += __shfl_xor_sync(FULLMASK, sc, d);
        msum += __shfl_xor_sync(FULLMASK, msum, d);
    }

    if (t == 0) {
        const int last = (int)(msum + 0.5f) - 1;
        long i0 = base, il = base + last;
        int tg0 = is64 ? tags32[2 * i0] : tags32[i0];
        int tgl = is64 ? tags32[2 * il] : tags32[il];
        const float score = sc + startT[tg0] + emis[i0 * T + tg0] + endT[tgl];
        atomicAdd(out, -score);            // out accumulates -sum(score)
    }
}

// ---------------- fused launch: fwd | bwd | score --------------------------
__global__ void __launch_bounds__(32) crf_fused_kernel(
    const float* __restrict__ emis,
    const int*   __restrict__ tags32,
    const float* __restrict__ mask,
    const float* __restrict__ trans,
    const float* __restrict__ startT,
    const float* __restrict__ endT,
    float* __restrict__ out,
    int B)
{
    __shared__ __align__(16) float pbuf[64];
    const int t = threadIdx.x;
    const int blk = blockIdx.x;

    if (blk < B) {
        run_dir<true >(blk, t, pbuf, emis, mask, trans, startT, endT);
    } else if (blk < 2 * B) {
        run_dir<false>(blk - B, t, pbuf, emis, mask, trans, startT, endT);
    } else {
        run_score(blk - 2 * B, t, emis, tags32, mask, trans, startT, endT, out);
    }
}

// ---------------- combine: alpha.beta dot -> partition ---------------------
__global__ void __launch_bounds__(32) crf_combine_kernel(float* __restrict__ out)
{
    constexpr float LN2 = 0.6931471805599453f;
    const int b = blockIdx.x;
    const int t = threadIdx.x;

    float p = g_vec[0][b][t] * g_vec[1][b][t];
    #pragma unroll
    for (int d = 16; d; d >>= 1) p += __shfl_xor_sync(FULLMASK, p, d);
    const float partition = (g_C[0][b] + g_C[1][b] + lg2f(p)) * LN2;

    if (t == 0) atomicAdd(out, partition);
}

extern "C" void kernel_launch(void* const* d_in, const int* in_sizes, int n_in,
                              void* d_out, int out_size) {
    const float* emis   = (const float*)d_in[0];   // [B,S,T] float32
    const int*   tags   = (const int*)  d_in[1];   // [B,S] int (32/64 detected)
    const float* mask   = (const float*)d_in[2];   // [B,S] float32
    const float* trans  = (const float*)d_in[3];   // [T,T]
    const float* startT = (const float*)d_in[4];   // [T]
    const float* endT   = (const float*)d_in[5];   // [T]
    float* out = (float*)d_out;

    const int B = in_sizes[2] / SFIX;              // mask elements = B*S

    cudaMemsetAsync(out, 0, sizeof(float));        // memset node, no kernel
    crf_fused_kernel<<<3 * B, 32>>>(emis, tags, mask, trans, startT, endT, out, B);
    crf_combine_kernel<<<B, 32>>>(out);
}